// round 10
// baseline (speedup 1.0000x reference)
#include <cuda_runtime.h>
#include <math.h>
#include <cstdint>

// Fused RoPE (positions == arange(S)); cp.async.bulk SMEM staging.
// R5-R9 showed the LDG path is latency-bound: in-flight bytes capped at
// warps x MLP x 16B because MLP costs registers. Bulk-copy staging holds
// 32KB in flight per CTA (7 CTAs/SM -> 224KB/SM) with ~35 regs.
//
// CTA = 2 seq-rows x 32 batches. One thread issues 32 x 1KB UBLKCP into
// SMEM with a single mbarrier expect_tx(32KB); trig computed during the
// copy; rotate from SMEM; STG.128 (streaming) to out.

#define BATCH 32
#define SEQ   4096
#define DK    128
#define QUADS (DK / 4)               // 32 float4 per row
#define ROWS  2                      // seq rows per CTA
#define TPB   128
#define TILE_BYTES (ROWS * DK * 4)   // 1024 B per batch slice
#define STAGE_BYTES (BATCH * TILE_BYTES)  // 32768 B

__device__ __forceinline__ uint32_t smem_u32(const void* p) {
    uint32_t a;
    asm("{ .reg .u64 t; cvta.to.shared.u64 t, %1; cvt.u32.u64 %0, t; }"
        : "=r"(a) : "l"(p));
    return a;
}

__global__ void __launch_bounds__(TPB) rope_bulk(
        const float* __restrict__ x, float4* __restrict__ out) {
    __shared__ __align__(16) float4 buf[BATCH * ROWS * QUADS];  // 32KB
    __shared__ __align__(8)  unsigned long long mbar;

    int tid = threadIdx.x;
    int s_base = blockIdx.x * ROWS;
    uint32_t mb = smem_u32(&mbar);

    if (tid == 0) {
        asm volatile("mbarrier.init.shared.b64 [%0], %1;"
                     :: "r"(mb), "r"(1) : "memory");
    }
    __syncthreads();

    if (tid == 0) {
        asm volatile("mbarrier.arrive.expect_tx.shared.b64 _, [%0], %1;"
                     :: "r"(mb), "r"((uint32_t)STAGE_BYTES) : "memory");
        const char* src0 = (const char*)(x + (size_t)s_base * DK);
        uint32_t dst0 = smem_u32(buf);
        uint32_t nbytes = TILE_BYTES;
#pragma unroll
        for (int b = 0; b < BATCH; b++) {
            asm volatile(
                "cp.async.bulk.shared::cta.global.mbarrier::complete_tx::bytes"
                " [%0], [%1], %2, [%3];"
                :: "r"(dst0 + b * TILE_BYTES),
                   "l"(src0 + (size_t)b * (SEQ * DK * 4)),
                   "r"(nbytes), "r"(mb)
                : "memory");
        }
    }

    // Trig while the bulk copies are in flight.
    int q   = tid & (QUADS - 1);
    int row = (tid >> 5) & (ROWS - 1);
    int bh  = tid >> 6;                 // batch half: 0 or 1
    int s   = s_base + row;

    const float C = -0.2076205059304601f;   // -log2(10000)/64
    float a0 = (float)s * exp2f((float)(2 * q)     * C);
    float a1 = (float)s * exp2f((float)(2 * q + 1) * C);
    float s0, c0, s1, c1;
    sincosf(a0, &s0, &c0);
    sincosf(a1, &s1, &c1);

    // Wait for all 32KB (phase 0).
    {
        uint32_t done;
        asm volatile(
            "{\n .reg .pred p;\n"
            " mbarrier.try_wait.parity.acquire.cta.shared::cta.b64 p, [%1], %2;\n"
            " selp.b32 %0, 1, 0, p;\n}"
            : "=r"(done) : "r"(mb), "r"(0u) : "memory");
        if (!done) {
            asm volatile(
                "{\n .reg .pred P1;\n"
                "WL_%=:\n"
                " mbarrier.try_wait.parity.acquire.cta.shared::cta.b64 P1, [%0], %1, 0x989680;\n"
                " @P1 bra.uni WD_%=;\n"
                " bra.uni WL_%=;\n"
                "WD_%=:\n}"
                :: "r"(mb), "r"(0u) : "memory");
        }
    }

#pragma unroll
    for (int i = 0; i < BATCH / 2; i++) {
        int b = bh * (BATCH / 2) + i;
        float4 v = buf[(b * ROWS + row) * QUADS + q];
        float4 r;
        r.x = c0 * v.x - s0 * v.y;
        r.y = s0 * v.x + c0 * v.y;
        r.z = c1 * v.z - s1 * v.w;
        r.w = s1 * v.z + c1 * v.w;
        __stcs(out + ((size_t)b * SEQ + s) * QUADS + q, r);
    }
}

extern "C" void kernel_launch(void* const* d_in, const int* in_sizes, int n_in,
                              void* d_out, int out_size) {
    const float* x = (const float*)d_in[0];
    // d_in[1] = token_positions (unused: reference overwrites with arange)
    // d_in[2] = rot (unused: trig recomputed on device)

    rope_bulk<<<SEQ / ROWS, TPB>>>(x, (float4*)d_out);   // 2048 CTAs
}

// round 11
// speedup vs baseline: 1.0128x; 1.0128x over previous
#include <cuda_runtime.h>
#include <math.h>

// Fused RoPE, positions == arange(S) (reference overwrites token_positions).
//   out[b,s,2k]   = cos(s*w_k)*x[b,s,2k] - sin(s*w_k)*x[b,s,2k+1]
//   out[b,s,2k+1] = sin(s*w_k)*x[b,s,2k] + cos(s*w_k)*x[b,s,2k+1]
//   w_k = 10000^(-k/64) = exp2(-k*log2(10000)/64)
//
// R10 post-mortem: bulk/SMEM staging regressed (occ 32%, serialized phases).
// Back to the R5 winner (MLP=4 front-batched, 256thr, ~38 regs), with ONE
// change: stores use __stwt (ST.E.WT). R8 traffic analysis: x is ~80%
// L2-resident across replays; the 64MB of output stores were allocating L2
// lines and evicting x (128MB > 126MB L2). Write-through stores don't
// allocate -> x stays fully resident, DRAM/launch drops ~77MB -> ~64MB.

#define BATCH   32
#define SEQ     4096
#define DK      128
#define QUADS   (DK / 4)            // 32 float4 per row
#define COLS    (SEQ * QUADS)       // 131072 (s,q) columns
#define BGROUP  4                   // batches per thread
#define NGROUPS (BATCH / BGROUP)    // 8

__global__ void __launch_bounds__(256) rope_fused(
        const float4* __restrict__ x, float4* __restrict__ out) {
    int idx = blockIdx.x * blockDim.x + threadIdx.x;   // 0 .. COLS*NGROUPS-1
    int col = idx & (COLS - 1);      // s*QUADS + q
    int g   = idx >> 17;             // batch group 0..7
    int q = col & (QUADS - 1);
    int s = col >> 5;

    const float4* xp = x   + (size_t)col + (size_t)g * (BGROUP * COLS);
    float4*       op = out + (size_t)col + (size_t)g * (BGROUP * COLS);

    // Front-batch all 4 loads (imm offsets): MLP=4, trig hides under latency.
    float4 v0 = xp[0];
    float4 v1 = xp[COLS];
    float4 v2 = xp[2 * COLS];
    float4 v3 = xp[3 * COLS];

    // -log2(10000)/64
    const float C = -0.2076205059304601f;
    float a0 = (float)s * exp2f((float)(2 * q)     * C);
    float a1 = (float)s * exp2f((float)(2 * q + 1) * C);

    float s0, c0, s1, c1;
    sincosf(a0, &s0, &c0);
    sincosf(a1, &s1, &c1);

    float4 r;
#define ROT_STORE(V, OFF)                      \
    r.x = c0 * (V).x - s0 * (V).y;             \
    r.y = s0 * (V).x + c0 * (V).y;             \
    r.z = c1 * (V).z - s1 * (V).w;             \
    r.w = s1 * (V).z + c1 * (V).w;             \
    __stwt(op + (OFF), r)

    ROT_STORE(v0, 0);
    ROT_STORE(v1, COLS);
    ROT_STORE(v2, 2 * COLS);
    ROT_STORE(v3, 3 * COLS);
#undef ROT_STORE
}

extern "C" void kernel_launch(void* const* d_in, const int* in_sizes, int n_in,
                              void* d_out, int out_size) {
    const float* x = (const float*)d_in[0];
    // d_in[1] = token_positions (unused: reference overwrites with arange)
    // d_in[2] = rot (unused: trig recomputed on device)

    int threads = 256;
    int total = COLS * NGROUPS;                  // 1,048,576 threads
    rope_fused<<<total / threads, threads>>>((const float4*)x, (float4*)d_out);
}